// round 1
// baseline (speedup 1.0000x reference)
#include <cuda_runtime.h>
#include <cuda_bf16.h>
#include <cstdint>
#include <cstdio>

#define IN_DIM   200
#define OUT_DIMX 2000
#define BATCHN   512
#define OUT_CH   32
#define KERN     9
#define L_OUTN   1992
#define FC_LENN  (OUT_CH * L_OUTN)   // 63744
#define NUM_ENTSN 100000
#define EPSV     1e-5f
#define KSPLIT   32                   // 32 * 1992 = 63744 exactly

// ---------------- scratch (device globals; no allocations) ----------------
__device__ float g_eWT[OUT_DIMX * IN_DIM];            // e_W transposed [2000,200]
__device__ float g_x0 [BATCHN * IN_DIM];              // bn0 output
__device__ float g_xa [BATCHN * OUT_DIMX];            // after GEMM1
__device__ float g_c  [(size_t)BATCHN * FC_LENN];     // conv output (130.5 MB)
__device__ float g_alpha[OUT_CH];
__device__ float g_betap[OUT_CH];
__device__ float g_ps [OUT_CH * 32];
__device__ float g_ps2[OUT_CH * 32];
__device__ float g_P  [(size_t)KSPLIT * BATCHN * IN_DIM]; // split-K partials (13 MB)
__device__ float g_z  [BATCHN * IN_DIM];              // bn2+tanh output

// ---------------- reductions ----------------
__device__ __forceinline__ float blockReduceSum(float v, float* s) {
    __syncthreads();
    #pragma unroll
    for (int o = 16; o; o >>= 1) v += __shfl_down_sync(0xffffffffu, v, o);
    int w = threadIdx.x >> 5, l = threadIdx.x & 31;
    if (l == 0) s[w] = v;
    __syncthreads();
    int nw = blockDim.x >> 5;
    if (w == 0) {
        float r = (l < nw) ? s[l] : 0.f;
        #pragma unroll
        for (int o = 16; o; o >>= 1) r += __shfl_down_sync(0xffffffffu, r, o);
        if (l == 0) s[0] = r;
    }
    __syncthreads();
    return s[0];
}

// ---------------- kernel 0: transpose e_W [200,2000] -> [2000,200] ----------------
__global__ void k_transpose(const float* __restrict__ W) {
    int i = blockIdx.x * blockDim.x + threadIdx.x;
    if (i < IN_DIM * OUT_DIMX) {
        int k = i / OUT_DIMX, n = i - k * OUT_DIMX;
        g_eWT[n * IN_DIM + k] = W[i];
    }
}

// ---------------- kernel 1: gather + bn0 ----------------
// grid = 200 (feature), block = 512 (batch)
__global__ void k_bn0(const float* __restrict__ E, const int* __restrict__ e1,
                      const float* __restrict__ g, const float* __restrict__ bt) {
    int f = blockIdx.x;
    int b = threadIdx.x;
    float v = E[(size_t)e1[b] * IN_DIM + f];
    __shared__ float sr[32];
    float s1 = blockReduceSum(v, sr);
    float s2 = blockReduceSum(v * v, sr);
    float m  = s1 * (1.f / BATCHN);
    float var = s2 * (1.f / BATCHN) - m * m;
    g_x0[b * IN_DIM + f] = (v - m) * rsqrtf(var + EPSV) * g[f] + bt[f];
}

// ---------------- kernel 2: conv1d per (b), all 32 channels ----------------
// grid = 512, block = 256
__global__ void k_conv(const float* __restrict__ R, const int* __restrict__ ridx) {
    int b = blockIdx.x;
    __shared__ float sx[OUT_DIMX];
    for (int i = threadIdx.x; i < OUT_DIMX; i += blockDim.x)
        sx[i] = g_xa[(size_t)b * OUT_DIMX + i];
    __syncthreads();
    const float* Rb = R + (size_t)ridx[b] * OUT_CH * KERN;
    for (int o = 0; o < OUT_CH; o++) {
        float r[KERN];
        #pragma unroll
        for (int k = 0; k < KERN; k++) r[k] = Rb[o * KERN + k];
        float* cp = g_c + ((size_t)b * OUT_CH + o) * L_OUTN;
        for (int l = threadIdx.x; l < L_OUTN; l += blockDim.x) {
            float s = 0.f;
            #pragma unroll
            for (int k = 0; k < KERN; k++) s += r[k] * sx[l + k];
            cp[l] = s;
        }
    }
}

// ---------------- kernel 3a/3b: bn1 statistics (deterministic 2-stage) ----------------
// grid = (32 channels, 32 batch-zones), block = 256
__global__ void k_bn1a() {
    int o = blockIdx.x, zb = blockIdx.y;
    float s = 0.f, s2 = 0.f;
    for (int b = zb * 16; b < zb * 16 + 16; b++) {
        const float* p = g_c + ((size_t)b * OUT_CH + o) * L_OUTN;
        for (int l = threadIdx.x; l < L_OUTN; l += blockDim.x) {
            float v = p[l]; s += v; s2 += v * v;
        }
    }
    __shared__ float sr[32];
    s  = blockReduceSum(s,  sr);
    s2 = blockReduceSum(s2, sr);
    if (threadIdx.x == 0) { g_ps[o * 32 + zb] = s; g_ps2[o * 32 + zb] = s2; }
}
// grid = 32, block = 32
__global__ void k_bn1b(const float* __restrict__ g1, const float* __restrict__ b1) {
    int o = blockIdx.x, l = threadIdx.x;
    float s = g_ps[o * 32 + l], s2 = g_ps2[o * 32 + l];
    #pragma unroll
    for (int off = 16; off; off >>= 1) {
        s  += __shfl_down_sync(0xffffffffu, s,  off);
        s2 += __shfl_down_sync(0xffffffffu, s2, off);
    }
    if (l == 0) {
        float Nf = (float)BATCHN * (float)L_OUTN;
        float m = s / Nf;
        float var = s2 / Nf - m * m;
        float a = rsqrtf(var + EPSV) * g1[o];
        g_alpha[o] = a;
        g_betap[o] = b1[o] - m * a;
    }
}

// ---------------- generic TN GEMM: C[m,n] = sum_k A[m,k]*B[n,k] ----------------
// 128x128 block tile, 8x8 microtile, KT=16 smem stage, optional split-K (gridDim.z)
// NORM: A element gets *g_alpha[o] + g_betap[o]; REQUIRES kChunk-aligned channel
//       boundaries (we launch with kChunk == L_OUTN so o == blockIdx.z, constant).
template<bool NORM, bool SIG>
__global__ __launch_bounds__(256) void k_gemm_tn(
    const float* __restrict__ A, const float* __restrict__ B, float* __restrict__ C,
    int M, int N, int K, int kChunk)
{
    constexpr int BM = 128, BN = 128, KT = 16;
    __shared__ float sA[KT][BM + 4];
    __shared__ float sB[KT][BN + 4];
    int m0 = blockIdx.x * BM, n0 = blockIdx.y * BN;
    int k0 = blockIdx.z * kChunk;
    int kend = min(k0 + kChunk, K);

    float nAl = 1.f, nBe = 0.f;
    if (NORM) { int o = k0 / L_OUTN; nAl = g_alpha[o]; nBe = g_betap[o]; }

    int t = threadIdx.x;
    int tm = t >> 4, tn = t & 15;       // 16x16 thread grid, each 8x8 outputs
    int lr = t >> 1, lk = (t & 1) * 8;  // load mapping: 128 rows x 2 half-chunks

    float acc[8][8];
    #pragma unroll
    for (int i = 0; i < 8; i++)
        #pragma unroll
        for (int j = 0; j < 8; j++) acc[i][j] = 0.f;

    for (int kb = k0; kb < kend; kb += KT) {
        // ---- stage A tile ----
        {
            int m = m0 + lr;
            const float* Ap = A + (size_t)m * K + (kb + lk);
            float rv[8];
            if (m < M && kb + KT <= kend) {
                float4 v0 = *(const float4*)Ap;
                float4 v1 = *(const float4*)(Ap + 4);
                rv[0]=v0.x; rv[1]=v0.y; rv[2]=v0.z; rv[3]=v0.w;
                rv[4]=v1.x; rv[5]=v1.y; rv[6]=v1.z; rv[7]=v1.w;
                if (NORM) {
                    #pragma unroll
                    for (int i = 0; i < 8; i++) rv[i] = rv[i] * nAl + nBe;
                }
            } else {
                #pragma unroll
                for (int i = 0; i < 8; i++) {
                    int kk = kb + lk + i;
                    float v = 0.f;
                    if (m < M && kk < kend) {
                        v = Ap[i];
                        if (NORM) v = v * nAl + nBe;
                    }
                    rv[i] = v;
                }
            }
            #pragma unroll
            for (int i = 0; i < 8; i++) sA[lk + i][lr] = rv[i];
        }
        // ---- stage B tile ----
        {
            int n = n0 + lr;
            const float* Bp = B + (size_t)n * K + (kb + lk);
            float rv[8];
            if (n < N && kb + KT <= kend) {
                float4 v0 = *(const float4*)Bp;
                float4 v1 = *(const float4*)(Bp + 4);
                rv[0]=v0.x; rv[1]=v0.y; rv[2]=v0.z; rv[3]=v0.w;
                rv[4]=v1.x; rv[5]=v1.y; rv[6]=v1.z; rv[7]=v1.w;
            } else {
                #pragma unroll
                for (int i = 0; i < 8; i++) {
                    int kk = kb + lk + i;
                    rv[i] = (n < N && kk < kend) ? Bp[i] : 0.f;
                }
            }
            #pragma unroll
            for (int i = 0; i < 8; i++) sB[lk + i][lr] = rv[i];
        }
        __syncthreads();
        #pragma unroll
        for (int kk = 0; kk < KT; kk++) {
            float a[8], b[8];
            #pragma unroll
            for (int i = 0; i < 8; i++) a[i] = sA[kk][tm * 8 + i];
            #pragma unroll
            for (int i = 0; i < 8; i++) b[i] = sB[kk][tn * 8 + i];
            #pragma unroll
            for (int i = 0; i < 8; i++)
                #pragma unroll
                for (int j = 0; j < 8; j++) acc[i][j] += a[i] * b[j];
        }
        __syncthreads();
    }

    float* Cz = C + (size_t)blockIdx.z * (size_t)M * (size_t)N;
    #pragma unroll
    for (int i = 0; i < 8; i++) {
        int m = m0 + tm * 8 + i;
        if (m >= M) continue;
        #pragma unroll
        for (int j = 0; j < 8; j++) {
            int n = n0 + tn * 8 + j;
            if (n >= N) continue;
            float v = acc[i][j];
            if (SIG) v = 1.f / (1.f + __expf(-v));
            Cz[(size_t)m * N + n] = v;
        }
    }
}

// ---------------- kernel 5: split-K reduce + bn2 + tanh ----------------
// grid = 200 (feature j), block = 512 (batch)
__global__ void k_bn2(const float* __restrict__ g2, const float* __restrict__ b2) {
    int j = blockIdx.x;
    int b = threadIdx.x;
    float y = 0.f;
    #pragma unroll
    for (int s = 0; s < KSPLIT; s++)
        y += g_P[((size_t)s * BATCHN + b) * IN_DIM + j];
    __shared__ float sr[32];
    float s1 = blockReduceSum(y, sr);
    float s2 = blockReduceSum(y * y, sr);
    float m   = s1 * (1.f / BATCHN);
    float var = s2 * (1.f / BATCHN) - m * m;
    g_z[b * IN_DIM + j] = tanhf((y - m) * rsqrtf(var + EPSV) * g2[j] + b2[j]);
}

// ---------------- launcher ----------------
extern "C" void kernel_launch(void* const* d_in, const int* in_sizes, int n_in,
                              void* d_out, int out_size) {
    const float* E   = (const float*)d_in[0];
    const float* R   = (const float*)d_in[1];
    const float* eW  = (const float*)d_in[2];
    const float* fcW = (const float*)d_in[3];
    const float* g0  = (const float*)d_in[4];
    const float* b0  = (const float*)d_in[5];
    const float* g1  = (const float*)d_in[6];
    const float* b1  = (const float*)d_in[7];
    const float* g2  = (const float*)d_in[8];
    const float* b2  = (const float*)d_in[9];
    const int*   e1  = (const int*)d_in[10];
    const int*   ri  = (const int*)d_in[11];
    float* out = (float*)d_out;

    float *eWT, *x0, *xa, *c, *P, *z;
    cudaGetSymbolAddress((void**)&eWT, g_eWT);
    cudaGetSymbolAddress((void**)&x0,  g_x0);
    cudaGetSymbolAddress((void**)&xa,  g_xa);
    cudaGetSymbolAddress((void**)&c,   g_c);
    cudaGetSymbolAddress((void**)&P,   g_P);
    cudaGetSymbolAddress((void**)&z,   g_z);

    // 0) transpose e_W -> [2000,200]
    k_transpose<<<(IN_DIM * OUT_DIMX + 255) / 256, 256>>>(eW);
    // 1) gather + bn0
    k_bn0<<<IN_DIM, BATCHN>>>(E, e1, g0, b0);
    // 2) GEMM1: x0[512,200] @ eWT^T -> xa[512,2000]
    k_gemm_tn<false, false><<<dim3(4, 16, 1), 256>>>(x0, eWT, xa, BATCHN, OUT_DIMX, IN_DIM, IN_DIM);
    // 3) conv
    k_conv<<<BATCHN, 256>>>(R, ri);
    // 4) bn1 stats
    k_bn1a<<<dim3(OUT_CH, 32), 256>>>();
    k_bn1b<<<OUT_CH, 32>>>(g1, b1);
    // 5) fc GEMM (normalized A on the fly), split-K=32, kChunk = 1992 (channel-aligned)
    k_gemm_tn<true, false><<<dim3(4, 2, KSPLIT), 256>>>(c, fcW, P, BATCHN, IN_DIM, FC_LENN, L_OUTN);
    // 6) reduce + bn2 + tanh
    k_bn2<<<IN_DIM, BATCHN>>>(g2, b2);
    // 7) logits GEMM + sigmoid -> d_out [512, 100000]
    k_gemm_tn<false, true><<<dim3(4, (NUM_ENTSN + 127) / 128, 1), 256>>>(z, E, out, BATCHN, NUM_ENTSN, IN_DIM, IN_DIM);

    (void)in_sizes; (void)n_in; (void)out_size;
}

// round 3
// speedup vs baseline: 2.9965x; 2.9965x over previous
#include <cuda_runtime.h>
#include <cuda_bf16.h>
#include <cstdint>

#define IN_DIM    200
#define OUT_DIMX  2000
#define BATCHN    512
#define OUT_CH    32
#define KERN      9
#define L_OUTN    1992
#define FC_LENN   (OUT_CH * L_OUTN)     // 63744
#define NUM_ENTSN 100000
#define EPSV      1e-5f
#define ZSPLIT    83                    // 83 * 768 = 63744
#define ZCHUNK    768
#define KPAD      256                   // padded K for logits GEMM

// ---------------- device scratch (no allocations allowed) ----------------
__device__ __align__(128) float g_eWT[OUT_DIMX * IN_DIM];
__device__ __align__(128) float g_x0 [BATCHN * IN_DIM];
__device__ __align__(128) float g_xa [BATCHN * OUT_DIMX];
__device__ __align__(128) __nv_bfloat16 g_cbf[(size_t)BATCHN * FC_LENN];    // 65.3MB
__device__ __align__(128) __nv_bfloat16 g_Ebf[(size_t)NUM_ENTSN * KPAD];    // 51.2MB
__device__ __align__(128) __nv_bfloat16 g_Wbf[(size_t)IN_DIM * FC_LENN];    // 25.5MB
__device__ __align__(128) float g_Pf [(size_t)ZSPLIT * BATCHN * IN_DIM];    // 34MB
__device__ __align__(128) float g_y  [BATCHN * IN_DIM];
__device__ __align__(128) __nv_bfloat16 g_zbf[BATCHN * KPAD];
__device__ float g_s1[OUT_CH * BATCHN];
__device__ float g_s2[OUT_CH * BATCHN];
__device__ float g_alpha[OUT_CH];
__device__ float g_betap[OUT_CH];

// ---------------- helpers ----------------
__device__ __forceinline__ uint32_t smem_u32(const void* p) {
    uint32_t a;
    asm("{ .reg .u64 t; cvta.to.shared.u64 t, %1; cvt.u32.u64 %0, t; }" : "=r"(a) : "l"(p));
    return a;
}
__device__ __forceinline__ void ldsm_x4(uint32_t* r, uint32_t addr) {
    asm volatile("ldmatrix.sync.aligned.m8n8.x4.shared.b16 {%0,%1,%2,%3}, [%4];"
                 : "=r"(r[0]), "=r"(r[1]), "=r"(r[2]), "=r"(r[3]) : "r"(addr));
}
__device__ __forceinline__ void ldsm_x2(uint32_t* r, uint32_t addr) {
    asm volatile("ldmatrix.sync.aligned.m8n8.x2.shared.b16 {%0,%1}, [%2];"
                 : "=r"(r[0]), "=r"(r[1]) : "r"(addr));
}
__device__ __forceinline__ void mma_bf16(float* c, const uint32_t* a, const uint32_t* b) {
    asm volatile("mma.sync.aligned.m16n8k16.row.col.f32.bf16.bf16.f32 "
                 "{%0,%1,%2,%3}, {%4,%5,%6,%7}, {%8,%9}, {%0,%1,%2,%3};"
                 : "+f"(c[0]), "+f"(c[1]), "+f"(c[2]), "+f"(c[3])
                 : "r"(a[0]), "r"(a[1]), "r"(a[2]), "r"(a[3]), "r"(b[0]), "r"(b[1]));
}

__device__ __forceinline__ float blockReduceSum(float v, float* s) {
    __syncthreads();
    #pragma unroll
    for (int o = 16; o; o >>= 1) v += __shfl_down_sync(0xffffffffu, v, o);
    int w = threadIdx.x >> 5, l = threadIdx.x & 31;
    if (l == 0) s[w] = v;
    __syncthreads();
    int nw = blockDim.x >> 5;
    if (w == 0) {
        float r = (l < nw) ? s[l] : 0.f;
        #pragma unroll
        for (int o = 16; o; o >>= 1) r += __shfl_down_sync(0xffffffffu, r, o);
        if (l == 0) s[0] = r;
    }
    __syncthreads();
    return s[0];
}

// ---------------- conversions ----------------
__global__ void k_cvtE(const float* __restrict__ E) {
    size_t i = (size_t)blockIdx.x * blockDim.x + threadIdx.x;
    if (i >= (size_t)NUM_ENTSN * KPAD) return;
    int col = (int)(i & (KPAD - 1));
    size_t row = i >> 8;
    g_Ebf[i] = (col < IN_DIM) ? __float2bfloat16(E[row * IN_DIM + col]) : __nv_bfloat16(0.f);
}
__global__ void k_cvtW(const float* __restrict__ W) {
    size_t i = (size_t)blockIdx.x * blockDim.x + threadIdx.x;
    if (i < (size_t)IN_DIM * FC_LENN) g_Wbf[i] = __float2bfloat16(W[i]);
}
__global__ void k_zpad() {
    int i = blockIdx.x * blockDim.x + threadIdx.x;
    if (i < BATCHN * (KPAD - IN_DIM)) {
        int b = i / (KPAD - IN_DIM), j = IN_DIM + i % (KPAD - IN_DIM);
        g_zbf[b * KPAD + j] = __nv_bfloat16(0.f);
    }
}
__global__ void k_transpose(const float* __restrict__ W) {
    int i = blockIdx.x * blockDim.x + threadIdx.x;
    if (i < IN_DIM * OUT_DIMX) {
        int k = i / OUT_DIMX, n = i - k * OUT_DIMX;
        g_eWT[n * IN_DIM + k] = W[i];
    }
}

// ---------------- gather + bn0 ----------------
__global__ void k_bn0(const float* __restrict__ E, const int* __restrict__ e1,
                      const float* __restrict__ g, const float* __restrict__ bt) {
    int f = blockIdx.x, b = threadIdx.x;
    float v = E[(size_t)e1[b] * IN_DIM + f];
    __shared__ float sr[32];
    float s1 = blockReduceSum(v, sr);
    float s2 = blockReduceSum(v * v, sr);
    float m = s1 * (1.f / BATCHN);
    float var = s2 * (1.f / BATCHN) - m * m;
    g_x0[b * IN_DIM + f] = (v - m) * rsqrtf(var + EPSV) * g[f] + bt[f];
}

// ---------------- fp32 SIMT GEMM (small GEMM1 only) ----------------
__global__ __launch_bounds__(256) void k_gemm1(
    const float* __restrict__ A, const float* __restrict__ B, float* __restrict__ C,
    int M, int N, int K)
{
    constexpr int KT = 16;
    __shared__ float sA[KT][132];
    __shared__ float sB[KT][132];
    int m0 = blockIdx.x * 128, n0 = blockIdx.y * 128;
    int t = threadIdx.x;
    int tm = t >> 4, tn = t & 15;
    int lr = t >> 1, lk = (t & 1) * 8;
    float acc[8][8];
    #pragma unroll
    for (int i = 0; i < 8; i++)
        #pragma unroll
        for (int j = 0; j < 8; j++) acc[i][j] = 0.f;
    for (int kb = 0; kb < K; kb += KT) {
        {
            int m = m0 + lr;
            const float* Ap = A + (size_t)m * K + (kb + lk);
            #pragma unroll
            for (int i = 0; i < 8; i++) {
                int kk = kb + lk + i;
                sA[lk + i][lr] = (m < M && kk < K) ? Ap[i] : 0.f;
            }
        }
        {
            int n = n0 + lr;
            const float* Bp = B + (size_t)n * K + (kb + lk);
            #pragma unroll
            for (int i = 0; i < 8; i++) {
                int kk = kb + lk + i;
                sB[lk + i][lr] = (n < N && kk < K) ? Bp[i] : 0.f;
            }
        }
        __syncthreads();
        #pragma unroll
        for (int kk = 0; kk < KT; kk++) {
            float a[8], b[8];
            #pragma unroll
            for (int i = 0; i < 8; i++) a[i] = sA[kk][tm * 8 + i];
            #pragma unroll
            for (int i = 0; i < 8; i++) b[i] = sB[kk][tn * 8 + i];
            #pragma unroll
            for (int i = 0; i < 8; i++)
                #pragma unroll
                for (int j = 0; j < 8; j++) acc[i][j] += a[i] * b[j];
        }
        __syncthreads();
    }
    #pragma unroll
    for (int i = 0; i < 8; i++) {
        int m = m0 + tm * 8 + i;
        if (m >= M) continue;
        #pragma unroll
        for (int j = 0; j < 8; j++) {
            int n = n0 + tn * 8 + j;
            if (n < N) C[(size_t)m * N + n] = acc[i][j];
        }
    }
}

// ---------------- bn1 stats via windowed autocorrelation ----------------
__global__ __launch_bounds__(256) void k_statsA(const float* __restrict__ R,
                                                const int* __restrict__ ridx) {
    int b = blockIdx.x, t = threadIdx.x;
    __shared__ float sx[OUT_DIMX];
    __shared__ float red[8][54];
    __shared__ float TG[54];
    for (int i = t; i < OUT_DIMX; i += 256) sx[i] = g_xa[(size_t)b * OUT_DIMX + i];
    __syncthreads();
    float acc[54];
    #pragma unroll
    for (int i = 0; i < 54; i++) acc[i] = 0.f;
    for (int l = t; l < L_OUTN; l += 256) {
        float xv[KERN];
        #pragma unroll
        for (int k = 0; k < KERN; k++) xv[k] = sx[l + k];
        #pragma unroll
        for (int k = 0; k < KERN; k++) acc[k] += xv[k];
        int p = 9;
        #pragma unroll
        for (int k = 0; k < KERN; k++)
            #pragma unroll
            for (int k2 = k; k2 < KERN; k2++) acc[p++] += xv[k] * xv[k2];
    }
    #pragma unroll
    for (int i = 0; i < 54; i++) {
        float v = acc[i];
        #pragma unroll
        for (int o = 16; o; o >>= 1) v += __shfl_down_sync(0xffffffffu, v, o);
        if ((t & 31) == 0) red[t >> 5][i] = v;
    }
    __syncthreads();
    if (t < 54) {
        float s = 0.f;
        #pragma unroll
        for (int w = 0; w < 8; w++) s += red[w][t];
        TG[t] = s;
    }
    __syncthreads();
    if (t < OUT_CH) {
        const float* Rb = R + (size_t)ridx[b] * OUT_CH * KERN + t * KERN;
        float r[KERN];
        #pragma unroll
        for (int k = 0; k < KERN; k++) r[k] = Rb[k];
        float s1 = 0.f, s2 = 0.f;
        #pragma unroll
        for (int k = 0; k < KERN; k++) s1 += r[k] * TG[k];
        int p = 9;
        #pragma unroll
        for (int k = 0; k < KERN; k++)
            #pragma unroll
            for (int k2 = k; k2 < KERN; k2++) {
                float c = (k2 == k) ? 1.f : 2.f;
                s2 += c * r[k] * r[k2] * TG[p++];
            }
        g_s1[t * BATCHN + b] = s1;
        g_s2[t * BATCHN + b] = s2;
    }
}
__global__ void k_statsB(const float* __restrict__ g1, const float* __restrict__ b1) {
    int o = blockIdx.x;
    __shared__ float sr[32];
    float s1 = blockReduceSum(g_s1[o * BATCHN + threadIdx.x], sr);
    float s2 = blockReduceSum(g_s2[o * BATCHN + threadIdx.x], sr);
    if (threadIdx.x == 0) {
        float Nf = (float)BATCHN * (float)L_OUTN;
        float m = s1 / Nf;
        float var = s2 / Nf - m * m;
        float a = rsqrtf(var + EPSV) * g1[o];
        g_alpha[o] = a;
        g_betap[o] = b1[o] - m * a;
    }
}

// ---------------- conv1d + bn1-affine -> bf16 ----------------
__global__ void k_conv(const float* __restrict__ R, const int* __restrict__ ridx) {
    int b = blockIdx.x;
    __shared__ float sx[OUT_DIMX];
    for (int i = threadIdx.x; i < OUT_DIMX; i += blockDim.x)
        sx[i] = g_xa[(size_t)b * OUT_DIMX + i];
    __syncthreads();
    const float* Rb = R + (size_t)ridx[b] * OUT_CH * KERN;
    for (int o = 0; o < OUT_CH; o++) {
        float r[KERN];
        #pragma unroll
        for (int k = 0; k < KERN; k++) r[k] = Rb[o * KERN + k];
        float al = g_alpha[o], be = g_betap[o];
        __nv_bfloat16* cp = g_cbf + (size_t)b * FC_LENN + o * L_OUTN;
        for (int l = threadIdx.x; l < L_OUTN; l += blockDim.x) {
            float s = 0.f;
            #pragma unroll
            for (int k = 0; k < KERN; k++) s += r[k] * sx[l + k];
            cp[l] = __float2bfloat16(s * al + be);
        }
    }
}

// ---------------- bf16 mma.sync TN GEMM ----------------
// C[m,n] = sum_k A[m,k0+k]*B[n,k0+k]; 128x128 CTA tile, 8 warps of 64x32.
#define KT 32
#define SROW (KT + 8)         // 40 halves = 80B row stride (16B aligned, conflict-free)
template<bool SIG>
__global__ __launch_bounds__(256) void k_wmma(
    const __nv_bfloat16* __restrict__ A, int lda,
    const __nv_bfloat16* __restrict__ B, int ldb, int Nvalid,
    float* __restrict__ C, long zStride, int ldc, int Kchunk)
{
    __shared__ __align__(16) __nv_bfloat16 sA[128 * SROW];
    __shared__ __align__(16) __nv_bfloat16 sB[128 * SROW];

    int t = threadIdx.x, lane = t & 31, wid = t >> 5;
    int wm = wid & 1, wn = wid >> 1;           // warp tile: rows wm*64, cols wn*32
    int m0 = blockIdx.x * 128, n0 = blockIdx.y * 128;
    long k0 = (long)blockIdx.z * Kchunk;

    // global load mapping: idx in [0,512): row=idx>>2, c8=idx&3 (8 halves each)
    int r0 = t >> 2, c80 = t & 3;
    int r1 = (t + 256) >> 2, c81 = c80;
    const __nv_bfloat16* Ag0 = A + (size_t)(m0 + r0) * lda + k0 + c80 * 8;
    const __nv_bfloat16* Ag1 = A + (size_t)(m0 + r1) * lda + k0 + c81 * 8;
    int nb0 = n0 + r0, nb1 = n0 + r1;
    const __nv_bfloat16* Bg0 = B + (size_t)nb0 * ldb + k0 + c80 * 8;
    const __nv_bfloat16* Bg1 = B + (size_t)nb1 * ldb + k0 + c81 * 8;
    bool bv0 = nb0 < Nvalid, bv1 = nb1 < Nvalid;

    uint32_t sA0 = smem_u32(sA), sB0 = smem_u32(sB);
    // ldmatrix lane addressing
    int rowA = lane & 15, colA = (lane >> 4) * 8;
    int rowB = lane & 7,  colB = ((lane >> 3) & 1) * 8;
    uint32_t uA[4], uB[4];
    #pragma unroll
    for (int mt = 0; mt < 4; mt++)
        uA[mt] = sA0 + (uint32_t)((wm * 64 + mt * 16 + rowA) * SROW + colA) * 2u;
    #pragma unroll
    for (int nt = 0; nt < 4; nt++)
        uB[nt] = sB0 + (uint32_t)((wn * 32 + nt * 8 + rowB) * SROW + colB) * 2u;

    float acc[4][4][4];
    #pragma unroll
    for (int i = 0; i < 4; i++)
        #pragma unroll
        for (int j = 0; j < 4; j++)
            #pragma unroll
            for (int q = 0; q < 4; q++) acc[i][j][q] = 0.f;

    uint4 pa0, pa1, pb0, pb1;
    const uint4 z4 = make_uint4(0, 0, 0, 0);
    // prefetch tile 0
    pa0 = *(const uint4*)Ag0;
    pa1 = *(const uint4*)Ag1;
    pb0 = bv0 ? *(const uint4*)Bg0 : z4;
    pb1 = bv1 ? *(const uint4*)Bg1 : z4;

    for (int kb = 0; kb < Kchunk; kb += KT) {
        *(uint4*)&sA[r0 * SROW + c80 * 8] = pa0;
        *(uint4*)&sA[r1 * SROW + c81 * 8] = pa1;
        *(uint4*)&sB[r0 * SROW + c80 * 8] = pb0;
        *(uint4*)&sB[r1 * SROW + c81 * 8] = pb1;
        __syncthreads();
        if (kb + KT < Kchunk) {
            pa0 = *(const uint4*)(Ag0 + kb + KT);
            pa1 = *(const uint4*)(Ag1 + kb + KT);
            pb0 = bv0 ? *(const uint4*)(Bg0 + kb + KT) : z4;
            pb1 = bv1 ? *(const uint4*)(Bg1 + kb + KT) : z4;
        }
        #pragma unroll
        for (int ks = 0; ks < 2; ks++) {
            uint32_t af[4][4], bf[4][2];
            #pragma unroll
            for (int mt = 0; mt < 4; mt++) ldsm_x4(af[mt], uA[mt] + ks * 32);
            #pragma unroll
            for (int nt = 0; nt < 4; nt++) ldsm_x2(bf[nt], uB[nt] + ks * 32);
            #pragma unroll
            for (int mt = 0; mt < 4; mt++)
                #pragma unroll
                for (int nt = 0; nt < 4; nt++) mma_bf16(acc[mt][nt], af[mt], bf[nt]);
        }
        __syncthreads();
    }

    // epilogue
    int gq = lane >> 2, gr = lane & 3;
    float* Cz = C + (long)blockIdx.z * zStride;
    #pragma unroll
    for (int mt = 0; mt < 4; mt++) {
        int m = m0 + wm * 64 + mt * 16 + gq;
        #pragma unroll
        for (int nt = 0; nt < 4; nt++) {
            int n = n0 + wn * 32 + nt * 8 + 2 * gr;
            if (n < Nvalid) {
                float2 v0 = make_float2(acc[mt][nt][0], acc[mt][nt][1]);
                float2 v1 = make_float2(acc[mt][nt][2], acc[mt][nt][3]);
                if (SIG) {
                    v0.x = 1.f / (1.f + __expf(-v0.x));
                    v0.y = 1.f / (1.f + __expf(-v0.y));
                    v1.x = 1.f / (1.f + __expf(-v1.x));
                    v1.y = 1.f / (1.f + __expf(-v1.y));
                }
                *(float2*)(Cz + (size_t)m * ldc + n) = v0;
                *(float2*)(Cz + (size_t)(m + 8) * ldc + n) = v1;
            }
        }
    }
}

// ---------------- split-K reduce (coalesced), then bn2 + tanh ----------------
__global__ void k_redP() {
    int i = blockIdx.x * blockDim.x + threadIdx.x;
    if (i < BATCHN * IN_DIM) {
        float y = 0.f;
        for (int z = 0; z < ZSPLIT; z++)
            y += g_Pf[(size_t)z * BATCHN * IN_DIM + i];
        g_y[i] = y;
    }
}
__global__ void k_bn2(const float* __restrict__ g2, const float* __restrict__ b2) {
    int j = blockIdx.x, b = threadIdx.x;
    float y = g_y[b * IN_DIM + j];
    __shared__ float sr[32];
    float s1 = blockReduceSum(y, sr);
    float s2 = blockReduceSum(y * y, sr);
    float m = s1 * (1.f / BATCHN);
    float var = s2 * (1.f / BATCHN) - m * m;
    float zz = tanhf((y - m) * rsqrtf(var + EPSV) * g2[j] + b2[j]);
    g_zbf[b * KPAD + j] = __float2bfloat16(zz);
}

// ---------------- launcher ----------------
extern "C" void kernel_launch(void* const* d_in, const int* in_sizes, int n_in,
                              void* d_out, int out_size) {
    const float* E   = (const float*)d_in[0];
    const float* R   = (const float*)d_in[1];
    const float* eW  = (const float*)d_in[2];
    const float* fcW = (const float*)d_in[3];
    const float* g0  = (const float*)d_in[4];
    const float* b0  = (const float*)d_in[5];
    const float* g1  = (const float*)d_in[6];
    const float* b1  = (const float*)d_in[7];
    const float* g2  = (const float*)d_in[8];
    const float* b2  = (const float*)d_in[9];
    const int*   e1  = (const int*)d_in[10];
    const int*   ri  = (const int*)d_in[11];
    float* out = (float*)d_out;

    float *eWT, *x0, *xa, *Pf;
    cudaGetSymbolAddress((void**)&eWT, g_eWT);
    cudaGetSymbolAddress((void**)&x0,  g_x0);
    cudaGetSymbolAddress((void**)&xa,  g_xa);
    cudaGetSymbolAddress((void**)&Pf,  g_Pf);
    __nv_bfloat16 *cbf, *Ebf, *Wbf, *zbf;
    cudaGetSymbolAddress((void**)&cbf, g_cbf);
    cudaGetSymbolAddress((void**)&Ebf, g_Ebf);
    cudaGetSymbolAddress((void**)&Wbf, g_Wbf);
    cudaGetSymbolAddress((void**)&zbf, g_zbf);

    // conversions
    k_transpose<<<(IN_DIM * OUT_DIMX + 255) / 256, 256>>>(eW);
    k_cvtE<<<(int)(((size_t)NUM_ENTSN * KPAD + 255) / 256), 256>>>(E);
    k_cvtW<<<(int)(((size_t)IN_DIM * FC_LENN + 255) / 256), 256>>>(fcW);
    k_zpad<<<(BATCHN * (KPAD - IN_DIM) + 255) / 256, 256>>>();

    // forward
    k_bn0<<<IN_DIM, BATCHN>>>(E, e1, g0, b0);
    k_gemm1<<<dim3(4, 16), 256>>>(x0, eWT, xa, BATCHN, OUT_DIMX, IN_DIM);
    k_statsA<<<BATCHN, 256>>>(R, ri);
    k_statsB<<<OUT_CH, BATCHN>>>(g1, b1);
    k_conv<<<BATCHN, 256>>>(R, ri);

    // fc GEMM: [512,200], K=63744 split into 83 chunks of 768
    k_wmma<false><<<dim3(4, 2, ZSPLIT), 256>>>(
        cbf, FC_LENN, Wbf, FC_LENN, IN_DIM, Pf, (long)BATCHN * IN_DIM, IN_DIM, ZCHUNK);

    k_redP<<<(BATCHN * IN_DIM + 255) / 256, 256>>>();
    k_bn2<<<IN_DIM, BATCHN>>>(g2, b2);

    // logits GEMM + sigmoid: [512,100000], K=256 (padded)
    k_wmma<true><<<dim3(4, (NUM_ENTSN + 127) / 128, 1), 256>>>(
        zbf, KPAD, Ebf, KPAD, NUM_ENTSN, out, 0L, NUM_ENTSN, KPAD);

    (void)in_sizes; (void)n_in; (void)out_size;
}

// round 4
// speedup vs baseline: 3.4626x; 1.1555x over previous
#include <cuda_runtime.h>
#include <cuda_bf16.h>
#include <cstdint>

#define IN_DIM    200
#define OUT_DIMX  2000
#define BATCHN    512
#define OUT_CH    32
#define KERN      9
#define L_OUTN    1992
#define FC_LENN   (OUT_CH * L_OUTN)     // 63744
#define NUM_ENTSN 100000
#define EPSV      1e-5f
#define ZSPLIT    83                    // 83 * 768 = 63744
#define ZCHUNK    768
#define KPAD2     224                   // smem-padded K for logits (7*32)

// ---------------- device scratch ----------------
__device__ __align__(128) float g_eWT[OUT_DIMX * IN_DIM];
__device__ __align__(128) float g_x0 [BATCHN * IN_DIM];
__device__ __align__(128) float g_xa [BATCHN * OUT_DIMX];
__device__ __align__(128) __nv_bfloat16 g_cbf[(size_t)BATCHN * FC_LENN];  // 65.3MB
__device__ __align__(128) float g_Pf [(size_t)ZSPLIT * BATCHN * IN_DIM];  // 34MB
__device__ __align__(128) float g_y  [BATCHN * IN_DIM];
__device__ __align__(128) __nv_bfloat16 g_zbf[BATCHN * KPAD2];
__device__ float g_s1[OUT_CH * BATCHN];
__device__ float g_s2[OUT_CH * BATCHN];
__device__ float g_alpha[OUT_CH];
__device__ float g_betap[OUT_CH];

// ---------------- helpers ----------------
__device__ __forceinline__ uint32_t smem_u32(const void* p) {
    uint32_t a;
    asm("{ .reg .u64 t; cvta.to.shared.u64 t, %1; cvt.u32.u64 %0, t; }" : "=r"(a) : "l"(p));
    return a;
}
__device__ __forceinline__ void ldsm_x4(uint32_t* r, uint32_t addr) {
    asm volatile("ldmatrix.sync.aligned.m8n8.x4.shared.b16 {%0,%1,%2,%3}, [%4];"
                 : "=r"(r[0]), "=r"(r[1]), "=r"(r[2]), "=r"(r[3]) : "r"(addr));
}
__device__ __forceinline__ void ldsm_x2(uint32_t* r, uint32_t addr) {
    asm volatile("ldmatrix.sync.aligned.m8n8.x2.shared.b16 {%0,%1}, [%2];"
                 : "=r"(r[0]), "=r"(r[1]) : "r"(addr));
}
__device__ __forceinline__ void mma_bf16(float* c, const uint32_t* a, const uint32_t* b) {
    asm volatile("mma.sync.aligned.m16n8k16.row.col.f32.bf16.bf16.f32 "
                 "{%0,%1,%2,%3}, {%4,%5,%6,%7}, {%8,%9}, {%0,%1,%2,%3};"
                 : "+f"(c[0]), "+f"(c[1]), "+f"(c[2]), "+f"(c[3])
                 : "r"(a[0]), "r"(a[1]), "r"(a[2]), "r"(a[3]), "r"(b[0]), "r"(b[1]));
}
__device__ __forceinline__ float blockReduceSum(float v, float* s) {
    __syncthreads();
    #pragma unroll
    for (int o = 16; o; o >>= 1) v += __shfl_down_sync(0xffffffffu, v, o);
    int w = threadIdx.x >> 5, l = threadIdx.x & 31;
    if (l == 0) s[w] = v;
    __syncthreads();
    int nw = blockDim.x >> 5;
    if (w == 0) {
        float r = (l < nw) ? s[l] : 0.f;
        #pragma unroll
        for (int o = 16; o; o >>= 1) r += __shfl_down_sync(0xffffffffu, r, o);
        if (l == 0) s[0] = r;
    }
    __syncthreads();
    return s[0];
}

// ---------------- tiny prep ----------------
__global__ void k_transpose(const float* __restrict__ W) {
    int i = blockIdx.x * blockDim.x + threadIdx.x;
    if (i < IN_DIM * OUT_DIMX) {
        int k = i / OUT_DIMX, n = i - k * OUT_DIMX;
        g_eWT[n * IN_DIM + k] = W[i];
    }
}

// ---------------- gather + bn0 ----------------
__global__ void k_bn0(const float* __restrict__ E, const int* __restrict__ e1,
                      const float* __restrict__ g, const float* __restrict__ bt) {
    int f = blockIdx.x, b = threadIdx.x;
    float v = E[(size_t)e1[b] * IN_DIM + f];
    __shared__ float sr[32];
    float s1 = blockReduceSum(v, sr);
    float s2 = blockReduceSum(v * v, sr);
    float m = s1 * (1.f / BATCHN);
    float var = s2 * (1.f / BATCHN) - m * m;
    g_x0[b * IN_DIM + f] = (v - m) * rsqrtf(var + EPSV) * g[f] + bt[f];
}

// ---------------- fp32 SIMT GEMM (small GEMM1 only) ----------------
__global__ __launch_bounds__(256) void k_gemm1(
    const float* __restrict__ A, const float* __restrict__ B, float* __restrict__ C,
    int M, int N, int K)
{
    constexpr int KT = 16;
    __shared__ float sA[KT][132];
    __shared__ float sB[KT][132];
    int m0 = blockIdx.x * 128, n0 = blockIdx.y * 128;
    int t = threadIdx.x;
    int tm = t >> 4, tn = t & 15;
    int lr = t >> 1, lk = (t & 1) * 8;
    float acc[8][8];
    #pragma unroll
    for (int i = 0; i < 8; i++)
        #pragma unroll
        for (int j = 0; j < 8; j++) acc[i][j] = 0.f;
    for (int kb = 0; kb < K; kb += KT) {
        {
            int m = m0 + lr;
            const float* Ap = A + (size_t)m * K + (kb + lk);
            #pragma unroll
            for (int i = 0; i < 8; i++) {
                int kk = kb + lk + i;
                sA[lk + i][lr] = (m < M && kk < K) ? Ap[i] : 0.f;
            }
        }
        {
            int n = n0 + lr;
            const float* Bp = B + (size_t)n * K + (kb + lk);
            #pragma unroll
            for (int i = 0; i < 8; i++) {
                int kk = kb + lk + i;
                sB[lk + i][lr] = (n < N && kk < K) ? Bp[i] : 0.f;
            }
        }
        __syncthreads();
        #pragma unroll
        for (int kk = 0; kk < KT; kk++) {
            float a[8], b[8];
            #pragma unroll
            for (int i = 0; i < 8; i++) a[i] = sA[kk][tm * 8 + i];
            #pragma unroll
            for (int i = 0; i < 8; i++) b[i] = sB[kk][tn * 8 + i];
            #pragma unroll
            for (int i = 0; i < 8; i++)
                #pragma unroll
                for (int j = 0; j < 8; j++) acc[i][j] += a[i] * b[j];
        }
        __syncthreads();
    }
    #pragma unroll
    for (int i = 0; i < 8; i++) {
        int m = m0 + tm * 8 + i;
        if (m >= M) continue;
        #pragma unroll
        for (int j = 0; j < 8; j++) {
            int n = n0 + tn * 8 + j;
            if (n < N) C[(size_t)m * N + n] = acc[i][j];
        }
    }
}

// ---------------- bn1 stats via windowed autocorrelation ----------------
__global__ __launch_bounds__(256) void k_statsA(const float* __restrict__ R,
                                                const int* __restrict__ ridx) {
    int b = blockIdx.x, t = threadIdx.x;
    __shared__ float sx[OUT_DIMX];
    __shared__ float red[8][54];
    __shared__ float TG[54];
    for (int i = t; i < OUT_DIMX; i += 256) sx[i] = g_xa[(size_t)b * OUT_DIMX + i];
    __syncthreads();
    float acc[54];
    #pragma unroll
    for (int i = 0; i < 54; i++) acc[i] = 0.f;
    for (int l = t; l < L_OUTN; l += 256) {
        float xv[KERN];
        #pragma unroll
        for (int k = 0; k < KERN; k++) xv[k] = sx[l + k];
        #pragma unroll
        for (int k = 0; k < KERN; k++) acc[k] += xv[k];
        int p = 9;
        #pragma unroll
        for (int k = 0; k < KERN; k++)
            #pragma unroll
            for (int k2 = k; k2 < KERN; k2++) acc[p++] += xv[k] * xv[k2];
    }
    #pragma unroll
    for (int i = 0; i < 54; i++) {
        float v = acc[i];
        #pragma unroll
        for (int o = 16; o; o >>= 1) v += __shfl_down_sync(0xffffffffu, v, o);
        if ((t & 31) == 0) red[t >> 5][i] = v;
    }
    __syncthreads();
    if (t < 54) {
        float s = 0.f;
        #pragma unroll
        for (int w = 0; w < 8; w++) s += red[w][t];
        TG[t] = s;
    }
    __syncthreads();
    if (t < OUT_CH) {
        const float* Rb = R + (size_t)ridx[b] * OUT_CH * KERN + t * KERN;
        float r[KERN];
        #pragma unroll
        for (int k = 0; k < KERN; k++) r[k] = Rb[k];
        float s1 = 0.f, s2 = 0.f;
        #pragma unroll
        for (int k = 0; k < KERN; k++) s1 += r[k] * TG[k];
        int p = 9;
        #pragma unroll
        for (int k = 0; k < KERN; k++)
            #pragma unroll
            for (int k2 = k; k2 < KERN; k2++) {
                float c = (k2 == k) ? 1.f : 2.f;
                s2 += c * r[k] * r[k2] * TG[p++];
            }
        g_s1[t * BATCHN + b] = s1;
        g_s2[t * BATCHN + b] = s2;
    }
}
__global__ void k_statsB(const float* __restrict__ g1, const float* __restrict__ b1) {
    int o = blockIdx.x;
    __shared__ float sr[32];
    float s1 = blockReduceSum(g_s1[o * BATCHN + threadIdx.x], sr);
    float s2 = blockReduceSum(g_s2[o * BATCHN + threadIdx.x], sr);
    if (threadIdx.x == 0) {
        float Nf = (float)BATCHN * (float)L_OUTN;
        float m = s1 / Nf;
        float var = s2 / Nf - m * m;
        float a = rsqrtf(var + EPSV) * g1[o];
        g_alpha[o] = a;
        g_betap[o] = b1[o] - m * a;
    }
}

// ---------------- conv1d + bn1-affine -> bf16 ----------------
__global__ void k_conv(const float* __restrict__ R, const int* __restrict__ ridx) {
    int b = blockIdx.x;
    __shared__ float sx[OUT_DIMX];
    for (int i = threadIdx.x; i < OUT_DIMX; i += blockDim.x)
        sx[i] = g_xa[(size_t)b * OUT_DIMX + i];
    __syncthreads();
    const float* Rb = R + (size_t)ridx[b] * OUT_CH * KERN;
    for (int o = 0; o < OUT_CH; o++) {
        float r[KERN];
        #pragma unroll
        for (int k = 0; k < KERN; k++) r[k] = Rb[o * KERN + k];
        float al = g_alpha[o], be = g_betap[o];
        __nv_bfloat16* cp = g_cbf + (size_t)b * FC_LENN + o * L_OUTN;
        for (int l = threadIdx.x; l < L_OUTN; l += blockDim.x) {
            float s = 0.f;
            #pragma unroll
            for (int k = 0; k < KERN; k++) s += r[k] * sx[l + k];
            cp[l] = __float2bfloat16(s * al + be);
        }
    }
}

// ---------------- 256x128 bf16 mma.sync TN GEMM, fp32 B converted on the fly ----
// C[m,n] = sum_k A[m,k0+k] * B[n,k0+k]
// A bf16 (rows always valid: M=512, gridDim.x=2), B fp32 guarded by Nvalid/Kvalid.
#define KT 32
#define SROW (KT + 8)         // 40 halves = 80B row stride
template<bool SIG>
__global__ __launch_bounds__(512) void k_wmma256(
    const __nv_bfloat16* __restrict__ A, int lda,
    const float* __restrict__ B, int ldb, int Nvalid, int Kvalid,
    float* __restrict__ C, long zStride, int ldc, int Kchunk)
{
    __shared__ __align__(16) __nv_bfloat16 sA[256 * SROW];
    __shared__ __align__(16) __nv_bfloat16 sB[128 * SROW];

    int t = threadIdx.x, lane = t & 31, wid = t >> 5;
    int wm = wid & 3, wn = wid >> 2;     // 4x4 warps; warp tile 64x32
    int m0 = blockIdx.x * 256, n0 = blockIdx.y * 128;
    long k0 = (long)blockIdx.z * Kchunk;

    // A load map: 512 thr -> 256 rows x 2 col-halves of 16 halves (32B)
    int ra = t >> 1, ca = (t & 1) * 16;
    const __nv_bfloat16* Ag = A + (size_t)(m0 + ra) * lda + k0 + ca;
    // B load map: 512 thr -> 128 rows x 4 groups of 8 floats
    int rb = t >> 2, cb = (t & 3) * 8;
    int nB = n0 + rb;
    const float* Bg = B + (size_t)nB * ldb + k0 + cb;
    bool nv = nB < Nvalid;

    uint32_t sA0 = smem_u32(sA), sB0 = smem_u32(sB);
    int rowA = lane & 15, colA = (lane >> 4) * 8;
    int rowB = lane & 7,  colB = ((lane >> 3) & 1) * 8;
    uint32_t uA[4], uB[4];
    #pragma unroll
    for (int mt = 0; mt < 4; mt++)
        uA[mt] = sA0 + (uint32_t)((wm * 64 + mt * 16 + rowA) * SROW + colA) * 2u;
    #pragma unroll
    for (int nt = 0; nt < 4; nt++)
        uB[nt] = sB0 + (uint32_t)((wn * 32 + nt * 8 + rowB) * SROW + colB) * 2u;

    float acc[4][4][4];
    #pragma unroll
    for (int i = 0; i < 4; i++)
        #pragma unroll
        for (int j = 0; j < 4; j++)
            #pragma unroll
            for (int q = 0; q < 4; q++) acc[i][j][q] = 0.f;

    const uint4 z4 = make_uint4(0, 0, 0, 0);
    const float4 zf = make_float4(0.f, 0.f, 0.f, 0.f);
    uint4 pa0, pa1;
    float4 pb0, pb1;

    // prefetch kb=0 (cb<=24 < Kvalid always since Kvalid>=200)
    pa0 = *(const uint4*)Ag;
    pa1 = *(const uint4*)(Ag + 8);
    pb0 = nv ? *(const float4*)Bg : zf;
    pb1 = nv ? *(const float4*)(Bg + 4) : zf;

    for (int kb = 0; kb < Kchunk; kb += KT) {
        *(uint4*)&sA[ra * SROW + ca] = pa0;
        *(uint4*)&sA[ra * SROW + ca + 8] = pa1;
        {
            __nv_bfloat162 h0 = __float22bfloat162_rn(make_float2(pb0.x, pb0.y));
            __nv_bfloat162 h1 = __float22bfloat162_rn(make_float2(pb0.z, pb0.w));
            __nv_bfloat162 h2 = __float22bfloat162_rn(make_float2(pb1.x, pb1.y));
            __nv_bfloat162 h3 = __float22bfloat162_rn(make_float2(pb1.z, pb1.w));
            uint4 v;
            v.x = *(uint32_t*)&h0; v.y = *(uint32_t*)&h1;
            v.z = *(uint32_t*)&h2; v.w = *(uint32_t*)&h3;
            *(uint4*)&sB[rb * SROW + cb] = v;
        }
        __syncthreads();
        if (kb + KT < Kchunk) {
            int kn = kb + KT;
            pa0 = *(const uint4*)(Ag + kn);
            pa1 = *(const uint4*)(Ag + kn + 8);
            bool kv = nv && (kn + cb < Kvalid);
            pb0 = kv ? *(const float4*)(Bg + kn) : zf;
            pb1 = kv ? *(const float4*)(Bg + kn + 4) : zf;
        }
        #pragma unroll
        for (int ks = 0; ks < 2; ks++) {
            uint32_t af[4][4], bf[4][2];
            #pragma unroll
            for (int mt = 0; mt < 4; mt++) ldsm_x4(af[mt], uA[mt] + ks * 32);
            #pragma unroll
            for (int nt = 0; nt < 4; nt++) ldsm_x2(bf[nt], uB[nt] + ks * 32);
            #pragma unroll
            for (int mt = 0; mt < 4; mt++)
                #pragma unroll
                for (int nt = 0; nt < 4; nt++) mma_bf16(acc[mt][nt], af[mt], bf[nt]);
        }
        __syncthreads();
    }

    // epilogue
    int gq = lane >> 2, gr = lane & 3;
    float* Cz = C + (long)blockIdx.z * zStride;
    #pragma unroll
    for (int mt = 0; mt < 4; mt++) {
        int m = m0 + wm * 64 + mt * 16 + gq;
        #pragma unroll
        for (int nt = 0; nt < 4; nt++) {
            int n = n0 + wn * 32 + nt * 8 + 2 * gr;
            if (n < Nvalid) {
                float2 v0 = make_float2(acc[mt][nt][0], acc[mt][nt][1]);
                float2 v1 = make_float2(acc[mt][nt][2], acc[mt][nt][3]);
                if (SIG) {
                    v0.x = 1.f / (1.f + __expf(-v0.x));
                    v0.y = 1.f / (1.f + __expf(-v0.y));
                    v1.x = 1.f / (1.f + __expf(-v1.x));
                    v1.y = 1.f / (1.f + __expf(-v1.y));
                }
                *(float2*)(Cz + (size_t)m * ldc + n) = v0;
                *(float2*)(Cz + (size_t)(m + 8) * ldc + n) = v1;
            }
        }
    }
}

// ---------------- split-K reduce, then bn2 + tanh (+K pad) ----------------
__global__ void k_redP() {
    int i = blockIdx.x * blockDim.x + threadIdx.x;
    if (i < BATCHN * IN_DIM) {
        float y = 0.f;
        for (int z = 0; z < ZSPLIT; z++)
            y += g_Pf[(size_t)z * BATCHN * IN_DIM + i];
        g_y[i] = y;
    }
}
__global__ void k_bn2(const float* __restrict__ g2, const float* __restrict__ b2) {
    int j = blockIdx.x, b = threadIdx.x;
    if (j >= IN_DIM) {                 // pad columns 200..223 with zeros
        g_zbf[b * KPAD2 + j] = __nv_bfloat16(0.f);
        return;
    }
    float y = g_y[b * IN_DIM + j];
    __shared__ float sr[32];
    float s1 = blockReduceSum(y, sr);
    float s2 = blockReduceSum(y * y, sr);
    float m = s1 * (1.f / BATCHN);
    float var = s2 * (1.f / BATCHN) - m * m;
    float zz = tanhf((y - m) * rsqrtf(var + EPSV) * g2[j] + b2[j]);
    g_zbf[b * KPAD2 + j] = __float2bfloat16(zz);
}

// ---------------- launcher ----------------
extern "C" void kernel_launch(void* const* d_in, const int* in_sizes, int n_in,
                              void* d_out, int out_size) {
    const float* E   = (const float*)d_in[0];
    const float* R   = (const float*)d_in[1];
    const float* eW  = (const float*)d_in[2];
    const float* fcW = (const float*)d_in[3];
    const float* g0  = (const float*)d_in[4];
    const float* b0  = (const float*)d_in[5];
    const float* g1  = (const float*)d_in[6];
    const float* b1  = (const float*)d_in[7];
    const float* g2  = (const float*)d_in[8];
    const float* b2  = (const float*)d_in[9];
    const int*   e1  = (const int*)d_in[10];
    const int*   ri  = (const int*)d_in[11];
    float* out = (float*)d_out;

    float *eWT, *x0, *xa, *Pf;
    cudaGetSymbolAddress((void**)&eWT, g_eWT);
    cudaGetSymbolAddress((void**)&x0,  g_x0);
    cudaGetSymbolAddress((void**)&xa,  g_xa);
    cudaGetSymbolAddress((void**)&Pf,  g_Pf);
    __nv_bfloat16 *cbf, *zbf;
    cudaGetSymbolAddress((void**)&cbf, g_cbf);
    cudaGetSymbolAddress((void**)&zbf, g_zbf);

    k_transpose<<<(IN_DIM * OUT_DIMX + 255) / 256, 256>>>(eW);
    k_bn0<<<IN_DIM, BATCHN>>>(E, e1, g0, b0);
    k_gemm1<<<dim3(4, 16), 256>>>(x0, eWT, xa, BATCHN, OUT_DIMX, IN_DIM);
    k_statsA<<<BATCHN, 256>>>(R, ri);
    k_statsB<<<OUT_CH, BATCHN>>>(g1, b1);
    k_conv<<<BATCHN, 256>>>(R, ri);

    // fc GEMM: A=cbf bf16, B=fcW fp32 on-the-fly; split-K 83 x 768
    k_wmma256<false><<<dim3(2, 2, ZSPLIT), 512>>>(
        cbf, FC_LENN, fcW, FC_LENN, IN_DIM, ZCHUNK,
        Pf, (long)BATCHN * IN_DIM, IN_DIM, ZCHUNK);

    k_redP<<<(BATCHN * IN_DIM + 255) / 256, 256>>>();
    k_bn2<<<KPAD2, BATCHN>>>(g2, b2);

    // logits GEMM + sigmoid: A=zbf (K padded to 224), B=E fp32 on-the-fly
    k_wmma256<true><<<dim3(2, (NUM_ENTSN + 127) / 128, 1), 512>>>(
        zbf, KPAD2, E, IN_DIM, NUM_ENTSN, IN_DIM,
        out, 0L, NUM_ENTSN, KPAD2);

    (void)in_sizes; (void)n_in; (void)out_size;
}